// round 13
// baseline (speedup 1.0000x reference)
#include <cuda_runtime.h>
#include <cuda_bf16.h>
#include <math_constants.h>
#include <cstdint>

#define SEQ 2048
#define HID 1024
#define NH  16
#define HD  64
#define QKV_N (3 * HID)

// ---------------------------------------------------------------------------
// Scratch (no dynamic allocation allowed)
// ---------------------------------------------------------------------------
// int8 quantized operands (two-level: x ~= s*(h + l/254))
__device__ __align__(128) int8_t g_Aqh[SEQ * HID];
__device__ __align__(128) int8_t g_Aql[SEQ * HID];
__device__ float g_Asc[SEQ];
__device__ __align__(128) int8_t g_Wqah[QKV_N * HID];
__device__ __align__(128) int8_t g_Wqal[QKV_N * HID];
__device__ float g_Wasc[QKV_N];
__device__ __align__(128) int8_t g_Wqph[HID * HID];
__device__ __align__(128) int8_t g_Wqpl[HID * HID];
__device__ float g_Wpsc[HID];
__device__ __align__(128) int8_t g_Cqh[SEQ * HID];
__device__ __align__(128) int8_t g_Cql[SEQ * HID];
__device__ float g_Csc[SEQ];
__device__ float g_part[16 * QKV_N];
__device__ __align__(128) float g_attnC[SEQ * HID];
// per-head QKV, bf16 hi/lo, layout [NH][SEQ][64]
__device__ __align__(128) __nv_bfloat16 g_Qh[NH * SEQ * HD];
__device__ __align__(128) __nv_bfloat16 g_Ql[NH * SEQ * HD];
__device__ __align__(128) __nv_bfloat16 g_Kh[NH * SEQ * HD];
__device__ __align__(128) __nv_bfloat16 g_Kl[NH * SEQ * HD];
__device__ __align__(128) __nv_bfloat16 g_Vh[NH * SEQ * HD];
__device__ __align__(128) __nv_bfloat16 g_Vl[NH * SEQ * HD];

// ---------------------------------------------------------------------------
// Helpers (baseline PTX only)
// ---------------------------------------------------------------------------
__device__ __forceinline__ uint32_t smem_u32(const void* p) {
    uint32_t a;
    asm("{ .reg .u64 t; cvta.to.shared.u64 t, %1; cvt.u32.u64 %0, t; }"
        : "=r"(a) : "l"(p));
    return a;
}
__device__ __forceinline__ void cp_async16(uint32_t dst, const void* src) {
    asm volatile("cp.async.cg.shared.global [%0], [%1], 16;"
                 :: "r"(dst), "l"(src));
}
#define CP_COMMIT() asm volatile("cp.async.commit_group;" ::: "memory")
#define CP_WAIT(n)  asm volatile("cp.async.wait_group %0;" :: "n"(n) : "memory")

__device__ __forceinline__ void ldm_x4(uint32_t* r, uint32_t addr) {
    asm volatile("ldmatrix.sync.aligned.m8n8.x4.shared.b16 {%0,%1,%2,%3}, [%4];"
                 : "=r"(r[0]), "=r"(r[1]), "=r"(r[2]), "=r"(r[3]) : "r"(addr));
}
__device__ __forceinline__ void ldm_x4_t(uint32_t* r, uint32_t addr) {
    asm volatile("ldmatrix.sync.aligned.m8n8.x4.trans.shared.b16 {%0,%1,%2,%3}, [%4];"
                 : "=r"(r[0]), "=r"(r[1]), "=r"(r[2]), "=r"(r[3]) : "r"(addr));
}
__device__ __forceinline__ void mma_bf16(float* d, const uint32_t* a,
                                         uint32_t b0, uint32_t b1) {
    asm volatile(
        "mma.sync.aligned.m16n8k16.row.col.f32.bf16.bf16.f32 "
        "{%0,%1,%2,%3}, {%4,%5,%6,%7}, {%8,%9}, {%0,%1,%2,%3};"
        : "+f"(d[0]), "+f"(d[1]), "+f"(d[2]), "+f"(d[3])
        : "r"(a[0]), "r"(a[1]), "r"(a[2]), "r"(a[3]), "r"(b0), "r"(b1));
}
__device__ __forceinline__ void mma_s8(int* d, const uint32_t* a,
                                       uint32_t b0, uint32_t b1) {
    asm volatile(
        "mma.sync.aligned.m16n8k32.row.col.s32.s8.s8.s32 "
        "{%0,%1,%2,%3}, {%4,%5,%6,%7}, {%8,%9}, {%0,%1,%2,%3};"
        : "+r"(d[0]), "+r"(d[1]), "+r"(d[2]), "+r"(d[3])
        : "r"(a[0]), "r"(a[1]), "r"(a[2]), "r"(a[3]), "r"(b0), "r"(b1));
}
__device__ __forceinline__ uint32_t pack_bf16(float a, float b) {
    __nv_bfloat162 t;
    t.x = __float2bfloat16(a);
    t.y = __float2bfloat16(b);
    return *reinterpret_cast<uint32_t*>(&t);
}

// ---------------------------------------------------------------------------
// Quantization kernels
// ---------------------------------------------------------------------------
// per-row two-level int8 quant: x = s*(h + l/254), s = rowmax/127
__global__ void quant_rows(const float* __restrict__ x, int K,
                           int8_t* __restrict__ h8, int8_t* __restrict__ l8,
                           float* __restrict__ sc) {
    const int row = blockIdx.x;
    const float* xr = x + (size_t)row * K;
    __shared__ float red[256];
    float mx = 0.0f;
    for (int i = threadIdx.x; i < K; i += 256) mx = fmaxf(mx, fabsf(xr[i]));
    red[threadIdx.x] = mx;
    __syncthreads();
    for (int s = 128; s > 0; s >>= 1) {
        if (threadIdx.x < s) red[threadIdx.x] = fmaxf(red[threadIdx.x], red[threadIdx.x + s]);
        __syncthreads();
    }
    const float scale = fmaxf(red[0], 1e-20f) / 127.0f;
    if (threadIdx.x == 0) sc[row] = scale;
    const float inv = 1.0f / scale;
    for (int i = threadIdx.x; i < K; i += 256) {
        float q = xr[i] * inv;
        float h = rintf(q);
        float l = rintf((q - h) * 254.0f);
        h8[(size_t)row * K + i] = (int8_t)(int)h;
        l8[(size_t)row * K + i] = (int8_t)(int)l;
    }
}

// partial column max of w[K,N] over 16 K-segments
__global__ void colmax_part(const float* __restrict__ w, int K, int N,
                            float* __restrict__ part) {
    int col = blockIdx.x * 256 + threadIdx.x;
    int seg = blockIdx.y;
    if (col >= N) return;
    int k0 = seg * (K / 16), k1 = k0 + K / 16;
    float mx = 0.0f;
    for (int k = k0; k < k1; k++) mx = fmaxf(mx, fabsf(w[(size_t)k * N + col]));
    part[seg * N + col] = mx;
}

// w[K,N] -> Bt[N,K] int8 h/l + per-col scale
__global__ void cvt_transpose_quant(const float* __restrict__ w,
                                    const float* __restrict__ part,
                                    int8_t* __restrict__ th, int8_t* __restrict__ tl,
                                    float* __restrict__ sc, int K, int N) {
    __shared__ float tile[32][33];
    int n0 = blockIdx.x * 32, k0 = blockIdx.y * 32;
    int tx = threadIdx.x, ty = threadIdx.y;
#pragma unroll
    for (int j = 0; j < 4; j++)
        tile[ty + 8 * j][tx] = w[(size_t)(k0 + ty + 8 * j) * N + n0 + tx];
    __syncthreads();
#pragma unroll
    for (int j = 0; j < 4; j++) {
        int n = n0 + ty + 8 * j;
        float mx = 0.0f;
#pragma unroll
        for (int p = 0; p < 16; p++) mx = fmaxf(mx, part[p * N + n]);
        float scale = fmaxf(mx, 1e-20f) / 127.0f;
        if (k0 == 0 && tx == 0) sc[n] = scale;
        float q = tile[tx][ty + 8 * j] / scale;
        float h = rintf(q);
        float l = rintf((q - h) * 254.0f);
        size_t o = (size_t)n * K + k0 + tx;
        th[o] = (int8_t)(int)h;
        tl[o] = (int8_t)(int)l;
    }
}

// ---------------------------------------------------------------------------
// int8 two-level GEMM via IMMA m16n8k32:
// C = (sa*sb) * (Ah*Bh + (Ah*Bl + Al*Bh)/254) + bias
// 512 threads (16 warps, 4/SMSP), warp tile 32x32, 4-stage cp.async pipeline.
// mode 0: fp32 C + bias. mode 1: QKV split hi/lo bf16 per head.
// ---------------------------------------------------------------------------
#define PITCH 80
#define MAT_BYTES (128 * PITCH)
#define STAGE_BYTES (4 * MAT_BYTES)   // 40960
#define NST 4

__global__ __launch_bounds__(512, 1) void gemm_imma_s8(
    int M, int N, int K, int mode,
    const int8_t* __restrict__ Ah, const int8_t* __restrict__ Al,
    const float* __restrict__ sa,
    const int8_t* __restrict__ Bh, const int8_t* __restrict__ Bl,
    const float* __restrict__ sb,
    const float* __restrict__ bias, float* __restrict__ C,
    __nv_bfloat16* __restrict__ qh, __nv_bfloat16* __restrict__ ql,
    __nv_bfloat16* __restrict__ kh, __nv_bfloat16* __restrict__ kl,
    __nv_bfloat16* __restrict__ vh, __nv_bfloat16* __restrict__ vl)
{
    extern __shared__ char sm[];
    const uint32_t sbase = smem_u32(sm);
    const int tid = threadIdx.x;
    const int lane = tid & 31;
    const int warp = tid >> 5;      // 0..15
    const int wm = warp & 3;        // 32-row band
    const int wn = warp >> 2;       // 32-col band
    const int m0 = blockIdx.y * 128;
    const int n0 = blockIdx.x * 128;

    const int8_t* srcs[4] = {
        Ah + (size_t)m0 * K, Al + (size_t)m0 * K,
        Bh + (size_t)n0 * K, Bl + (size_t)n0 * K };

    int accH[2][4][4], accX[2][4][4];
#pragma unroll
    for (int i = 0; i < 2; i++)
#pragma unroll
        for (int j = 0; j < 4; j++)
#pragma unroll
            for (int q = 0; q < 4; q++) { accH[i][j][q] = 0; accX[i][j][q] = 0; }

    // stage: 4 mats x 128 rows x 64 bytes (BK = 64 int8)
    auto load_stage = [&](int s, int kc) {
#pragma unroll
        for (int i = 0; i < 4; i++) {
            int t = tid + i * 512;
            int mat = t >> 9;
            int r = (t >> 2) & 127;
            int ch = t & 3;
            cp_async16(sbase + s * STAGE_BYTES + mat * MAT_BYTES + r * PITCH + ch * 16,
                       srcs[mat] + (size_t)r * K + kc * 64 + ch * 16);
        }
    };

    const int NC = K / 64;
#pragma unroll
    for (int s = 0; s < NST - 1; s++) {
        load_stage(s, s);
        CP_COMMIT();
    }

    const int g = lane >> 3;
    const int rl = lane & 7;

    for (int c = 0; c < NC; c++) {
        CP_WAIT(NST - 2);
        __syncthreads();

        const uint32_t st = sbase + (c % NST) * STAGE_BYTES;

#pragma unroll
        for (int kb = 0; kb < 2; kb++) {          // two k32 blocks per chunk
            const int ch = kb * 2 + (g >> 1);
            const int roff = rl + ((g & 1) << 3);

            uint32_t ah[2][4], al_[2][4];
#pragma unroll
            for (int mf = 0; mf < 2; mf++) {
                int row = wm * 32 + mf * 16 + roff;
                ldm_x4(ah[mf],  st + 0 * MAT_BYTES + row * PITCH + ch * 16);
                ldm_x4(al_[mf], st + 1 * MAT_BYTES + row * PITCH + ch * 16);
            }

            uint32_t bh_[4][2], bl_[4][2];
#pragma unroll
            for (int ng = 0; ng < 2; ng++) {
                int row = wn * 32 + ng * 16 + roff;
                uint32_t r4[4], r5[4];
                ldm_x4(r4, st + 2 * MAT_BYTES + row * PITCH + ch * 16);
                ldm_x4(r5, st + 3 * MAT_BYTES + row * PITCH + ch * 16);
                bh_[2 * ng][0] = r4[0];     bh_[2 * ng][1] = r4[2];
                bh_[2 * ng + 1][0] = r4[1]; bh_[2 * ng + 1][1] = r4[3];
                bl_[2 * ng][0] = r5[0];     bl_[2 * ng][1] = r5[2];
                bl_[2 * ng + 1][0] = r5[1]; bl_[2 * ng + 1][1] = r5[3];
            }

            // term-major, independent accumulators
#pragma unroll
            for (int mf = 0; mf < 2; mf++)
#pragma unroll
                for (int nf = 0; nf < 4; nf++)
                    mma_s8(accH[mf][nf], ah[mf],  bh_[nf][0], bh_[nf][1]);
#pragma unroll
            for (int mf = 0; mf < 2; mf++)
#pragma unroll
                for (int nf = 0; nf < 4; nf++)
                    mma_s8(accX[mf][nf], ah[mf],  bl_[nf][0], bl_[nf][1]);
#pragma unroll
            for (int mf = 0; mf < 2; mf++)
#pragma unroll
                for (int nf = 0; nf < 4; nf++)
                    mma_s8(accX[mf][nf], al_[mf], bh_[nf][0], bh_[nf][1]);
        }

        if (c + NST - 1 < NC)
            load_stage((c + NST - 1) % NST, c + NST - 1);
        CP_COMMIT();
    }

    // Epilogue
#pragma unroll
    for (int mf = 0; mf < 2; mf++) {
        int rbase = m0 + wm * 32 + mf * 16 + (lane >> 2);
        float fa0 = sa[rbase], fa1 = sa[rbase + 8];
#pragma unroll
        for (int nf = 0; nf < 4; nf++) {
            int col = n0 + wn * 32 + nf * 8 + (lane & 3) * 2;
            float fb0 = sb[col], fb1 = sb[col + 1];
            float2 bv = *reinterpret_cast<const float2*>(&bias[col]);
            const float r254 = 1.0f / 254.0f;
            float a0 = fa0 * fb0 * ((float)accH[mf][nf][0] + (float)accX[mf][nf][0] * r254) + bv.x;
            float a1 = fa0 * fb1 * ((float)accH[mf][nf][1] + (float)accX[mf][nf][1] * r254) + bv.y;
            float a2 = fa1 * fb0 * ((float)accH[mf][nf][2] + (float)accX[mf][nf][2] * r254) + bv.x;
            float a3 = fa1 * fb1 * ((float)accH[mf][nf][3] + (float)accX[mf][nf][3] * r254) + bv.y;
            if (mode == 0) {
                float2 o0 = {a0, a1}, o1 = {a2, a3};
                *reinterpret_cast<float2*>(&C[(size_t)rbase * N + col]) = o0;
                *reinterpret_cast<float2*>(&C[(size_t)(rbase + 8) * N + col]) = o1;
            } else {
                int sec = col >> 10;
                int head = (col & 1023) >> 6;
                int dim = col & 63;
                __nv_bfloat16* dh = (sec == 0) ? qh : (sec == 1) ? kh : vh;
                __nv_bfloat16* dl = (sec == 0) ? ql : (sec == 1) ? kl : vl;
                size_t o0 = ((size_t)head * SEQ + rbase) * HD + dim;
                size_t o1 = o0 + 8 * HD;
                __nv_bfloat16 h0 = __float2bfloat16(a0), h1 = __float2bfloat16(a1);
                __nv_bfloat16 h2 = __float2bfloat16(a2), h3 = __float2bfloat16(a3);
                *reinterpret_cast<uint32_t*>(&dh[o0]) = pack_bf16(a0, a1);
                *reinterpret_cast<uint32_t*>(&dl[o0]) =
                    pack_bf16(a0 - __bfloat162float(h0), a1 - __bfloat162float(h1));
                *reinterpret_cast<uint32_t*>(&dh[o1]) = pack_bf16(a2, a3);
                *reinterpret_cast<uint32_t*>(&dl[o1]) =
                    pack_bf16(a2 - __bfloat162float(h2), a3 - __bfloat162float(h3));
            }
        }
    }
}

// ---------------------------------------------------------------------------
// Tensorized causal flash attention (bf16 hi/lo), unchanged compute;
// epilogue now writes fp32 C (proj input is re-quantized to int8).
// ---------------------------------------------------------------------------
__global__ __launch_bounds__(256, 1) void attn_mma(
    const __nv_bfloat16* __restrict__ Qh_, const __nv_bfloat16* __restrict__ Ql_,
    const __nv_bfloat16* __restrict__ Kh_, const __nv_bfloat16* __restrict__ Kl_,
    const __nv_bfloat16* __restrict__ Vh_, const __nv_bfloat16* __restrict__ Vl_,
    float* __restrict__ C)
{
    extern __shared__ char sm[];
    const uint32_t sb = smem_u32(sm);
    const int h = blockIdx.y;
    const int qb = blockIdx.x;
    const int tid = threadIdx.x;
    const int lane = tid & 31;
    const int warp = tid >> 5;
    const int qbase = qb * 128;
    const size_t hb = (size_t)h * SEQ * HD;
    const float scale = 0.125f;

    const __nv_bfloat16* kv[4] = { Kh_ + hb, Kl_ + hb, Vh_ + hb, Vl_ + hb };

    for (int i = tid; i < 128 * 8; i += 256) {
        int r = i >> 3, ch = i & 7;
        uint32_t sw = (uint32_t)((ch ^ (r & 7)) * 16);
        const size_t go = hb + (size_t)(qbase + r) * HD + ch * 8;
        cp_async16(sb + r * 128 + sw, Qh_ + go);
        cp_async16(sb + 16384 + r * 128 + sw, Ql_ + go);
    }
    CP_COMMIT(); CP_WAIT(0);
    __syncthreads();

    uint32_t qh[4][4], ql[4][4];
    {
        int row = warp * 16 + (lane & 15);
#pragma unroll
        for (int ks = 0; ks < 4; ks++) {
            int ch = ks * 2 + (lane >> 4);
            uint32_t a = sb + row * 128 + ((ch ^ (row & 7)) * 16);
            ldm_x4(qh[ks], a);
            ldm_x4(ql[ks], a + 16384);
        }
    }
    __syncthreads();

    float o[8][4];
#pragma unroll
    for (int i = 0; i < 8; i++)
#pragma unroll
        for (int j = 0; j < 4; j++) o[i][j] = 0.0f;
    float m0v = -CUDART_INF_F, m1v = -CUDART_INF_F;
    float l0v = 0.0f, l1v = 0.0f;

    auto load_kv = [&](int s, int t) {
#pragma unroll
        for (int i = 0; i < 8; i++) {
            int idx = tid + i * 256;
            int mat = idx >> 9;
            int r = (idx >> 3) & 63;
            int ch = idx & 7;
            cp_async16(sb + s * 32768 + mat * 8192 + r * 128 + ((ch ^ (r & 7)) * 16),
                       kv[mat] + (size_t)(t * 64 + r) * HD + ch * 8);
        }
        CP_COMMIT();
    };

    load_kv(0, 0);

    const int ntiles = 2 * qb + 2;
    for (int t = 0; t < ntiles; t++) {
        if (t + 1 < ntiles) {
            load_kv((t + 1) & 1, t + 1);
            CP_WAIT(1);
        } else {
            CP_WAIT(0);
        }
        __syncthreads();

        const uint32_t st = sb + (t & 1) * 32768;
        const bool active = (t * 64 <= qbase + warp * 16 + 15);

        if (active) {
            float s[8][4];
#pragma unroll
            for (int i = 0; i < 8; i++)
#pragma unroll
                for (int j = 0; j < 4; j++) s[i][j] = 0.0f;

#pragma unroll
            for (int ks = 0; ks < 4; ks++) {
#pragma unroll
                for (int kp = 0; kp < 2; kp++) {
                    uint32_t rh[2][4], rl[2][4];
#pragma unroll
                    for (int j = 0; j < 2; j++) {
                        int key = (kp * 2 + j) * 16 + (lane & 15);
                        int ch = ks * 2 + (lane >> 4);
                        uint32_t a = st + key * 128 + ((ch ^ (key & 7)) * 16);
                        ldm_x4(rh[j], a);
                        ldm_x4(rl[j], a + 8192);
                    }
                    float* s0 = s[4 * kp + 0];
                    float* s1 = s[4 * kp + 1];
                    float* s2 = s[4 * kp + 2];
                    float* s3 = s[4 * kp + 3];
                    mma_bf16(s0, qh[ks], rh[0][0], rh[0][2]);
                    mma_bf16(s1, qh[ks], rh[0][1], rh[0][3]);
                    mma_bf16(s2, qh[ks], rh[1][0], rh[1][2]);
                    mma_bf16(s3, qh[ks], rh[1][1], rh[1][3]);
                    mma_bf16(s0, qh[ks], rl[0][0], rl[0][2]);
                    mma_bf16(s1, qh[ks], rl[0][1], rl[0][3]);
                    mma_bf16(s2, qh[ks], rl[1][0], rl[1][2]);
                    mma_bf16(s3, qh[ks], rl[1][1], rl[1][3]);
                    mma_bf16(s0, ql[ks], rh[0][0], rh[0][2]);
                    mma_bf16(s1, ql[ks], rh[0][1], rh[0][3]);
                    mma_bf16(s2, ql[ks], rh[1][0], rh[1][2]);
                    mma_bf16(s3, ql[ks], rh[1][1], rh[1][3]);
                }
            }

            const bool masked = (t >= 2 * qb);
            const int gr = lane >> 2;
            const int c2 = (lane & 3) * 2;
            const int gq0 = qbase + warp * 16 + gr;
            float mx0 = -CUDART_INF_F, mx1 = -CUDART_INF_F;
#pragma unroll
            for (int nf = 0; nf < 8; nf++) {
#pragma unroll
                for (int j = 0; j < 2; j++) {
                    s[nf][j]     *= scale;
                    s[nf][2 + j] *= scale;
                    if (masked) {
                        int gk = t * 64 + nf * 8 + c2 + j;
                        if (gk > gq0)     s[nf][j]     = -CUDART_INF_F;
                        if (gk > gq0 + 8) s[nf][2 + j] = -CUDART_INF_F;
                    }
                    mx0 = fmaxf(mx0, s[nf][j]);
                    mx1 = fmaxf(mx1, s[nf][2 + j]);
                }
            }
            mx0 = fmaxf(mx0, __shfl_xor_sync(0xffffffffu, mx0, 1));
            mx0 = fmaxf(mx0, __shfl_xor_sync(0xffffffffu, mx0, 2));
            mx1 = fmaxf(mx1, __shfl_xor_sync(0xffffffffu, mx1, 1));
            mx1 = fmaxf(mx1, __shfl_xor_sync(0xffffffffu, mx1, 2));

            float mn0 = fmaxf(m0v, mx0), mn1 = fmaxf(m1v, mx1);
            float sum0 = 0.0f, sum1 = 0.0f;
#pragma unroll
            for (int nf = 0; nf < 8; nf++) {
#pragma unroll
                for (int j = 0; j < 2; j++) {
                    float p0 = __expf(s[nf][j] - mn0);
                    float p1 = __expf(s[nf][2 + j] - mn1);
                    s[nf][j] = p0;
                    s[nf][2 + j] = p1;
                    sum0 += p0;
                    sum1 += p1;
                }
            }
            sum0 += __shfl_xor_sync(0xffffffffu, sum0, 1);
            sum0 += __shfl_xor_sync(0xffffffffu, sum0, 2);
            sum1 += __shfl_xor_sync(0xffffffffu, sum1, 1);
            sum1 += __shfl_xor_sync(0xffffffffu, sum1, 2);

            float corr0 = __expf(m0v - mn0), corr1 = __expf(m1v - mn1);
            l0v = l0v * corr0 + sum0;
            l1v = l1v * corr1 + sum1;
            m0v = mn0; m1v = mn1;
#pragma unroll
            for (int nf = 0; nf < 8; nf++) {
                o[nf][0] *= corr0; o[nf][1] *= corr0;
                o[nf][2] *= corr1; o[nf][3] *= corr1;
            }

#pragma unroll
            for (int ks = 0; ks < 4; ks++) {
                uint32_t pah[4], pal[4];
#pragma unroll
                for (int half = 0; half < 2; half++) {
                    float p0 = s[2 * ks + half][0], p1 = s[2 * ks + half][1];
                    float p2 = s[2 * ks + half][2], p3 = s[2 * ks + half][3];
                    __nv_bfloat16 h0 = __float2bfloat16(p0), h1 = __float2bfloat16(p1);
                    __nv_bfloat16 h2 = __float2bfloat16(p2), h3 = __float2bfloat16(p3);
                    pah[half * 2]     = pack_bf16(p0, p1);
                    pah[half * 2 + 1] = pack_bf16(p2, p3);
                    pal[half * 2]     = pack_bf16(p0 - __bfloat162float(h0),
                                                  p1 - __bfloat162float(h1));
                    pal[half * 2 + 1] = pack_bf16(p2 - __bfloat162float(h2),
                                                  p3 - __bfloat162float(h3));
                }
#pragma unroll
                for (int dp = 0; dp < 2; dp++) {
                    uint32_t rh[2][4], rl[2][4];
#pragma unroll
                    for (int j = 0; j < 2; j++) {
                        int dg = dp * 2 + j;
                        int key = ks * 16 + (lane & 15);
                        int ch = dg * 2 + (lane >> 4);
                        uint32_t a = st + 16384 + key * 128 + ((ch ^ (key & 7)) * 16);
                        ldm_x4_t(rh[j], a);
                        ldm_x4_t(rl[j], a + 8192);
                    }
                    float* o0 = o[4 * dp + 0];
                    float* o1 = o[4 * dp + 1];
                    float* o2 = o[4 * dp + 2];
                    float* o3 = o[4 * dp + 3];
                    mma_bf16(o0, pah, rh[0][0], rh[0][1]);
                    mma_bf16(o1, pah, rh[0][2], rh[0][3]);
                    mma_bf16(o2, pah, rh[1][0], rh[1][1]);
                    mma_bf16(o3, pah, rh[1][2], rh[1][3]);
                    mma_bf16(o0, pah, rl[0][0], rl[0][1]);
                    mma_bf16(o1, pah, rl[0][2], rl[0][3]);
                    mma_bf16(o2, pah, rl[1][0], rl[1][1]);
                    mma_bf16(o3, pah, rl[1][2], rl[1][3]);
                    mma_bf16(o0, pal, rh[0][0], rh[0][1]);
                    mma_bf16(o1, pal, rh[0][2], rh[0][3]);
                    mma_bf16(o2, pal, rh[1][0], rh[1][1]);
                    mma_bf16(o3, pal, rh[1][2], rh[1][3]);
                }
            }
        }
        __syncthreads();
    }

    // ---- Finalize: fp32 out ----
    const float inv0 = 1.0f / l0v, inv1 = 1.0f / l1v;
    const int row0 = qbase + warp * 16 + (lane >> 2);
    const int col0 = h * HD + (lane & 3) * 2;
#pragma unroll
    for (int nf = 0; nf < 8; nf++) {
        int col = col0 + nf * 8;
        float2 w0 = { o[nf][0] * inv0, o[nf][1] * inv0 };
        float2 w1 = { o[nf][2] * inv1, o[nf][3] * inv1 };
        *reinterpret_cast<float2*>(&C[(size_t)row0 * HID + col]) = w0;
        *reinterpret_cast<float2*>(&C[(size_t)(row0 + 8) * HID + col]) = w1;
    }
}

// ---------------------------------------------------------------------------
extern "C" void kernel_launch(void* const* d_in, const int* in_sizes, int n_in,
                              void* d_out, int out_size)
{
    const float* H  = (const float*)d_in[0];
    const float* Wa = (const float*)d_in[1];
    const float* ba = (const float*)d_in[2];
    const float* Wp = (const float*)d_in[3];
    const float* bp = (const float*)d_in[4];
    float* out = (float*)d_out;

    int8_t *Aqh, *Aql, *Wqah, *Wqal, *Wqph, *Wqpl, *Cqh, *Cql;
    float *Asc, *Wasc, *Wpsc, *Csc, *part, *attnC;
    __nv_bfloat16 *Qh, *Ql, *Kh, *Kl, *Vh, *Vl;
    cudaGetSymbolAddress((void**)&Aqh, g_Aqh);
    cudaGetSymbolAddress((void**)&Aql, g_Aql);
    cudaGetSymbolAddress((void**)&Asc, g_Asc);
    cudaGetSymbolAddress((void**)&Wqah, g_Wqah);
    cudaGetSymbolAddress((void**)&Wqal, g_Wqal);
    cudaGetSymbolAddress((void**)&Wasc, g_Wasc);
    cudaGetSymbolAddress((void**)&Wqph, g_Wqph);
    cudaGetSymbolAddress((void**)&Wqpl, g_Wqpl);
    cudaGetSymbolAddress((void**)&Wpsc, g_Wpsc);
    cudaGetSymbolAddress((void**)&Cqh, g_Cqh);
    cudaGetSymbolAddress((void**)&Cql, g_Cql);
    cudaGetSymbolAddress((void**)&Csc, g_Csc);
    cudaGetSymbolAddress((void**)&part, g_part);
    cudaGetSymbolAddress((void**)&attnC, g_attnC);
    cudaGetSymbolAddress((void**)&Qh, g_Qh);
    cudaGetSymbolAddress((void**)&Ql, g_Ql);
    cudaGetSymbolAddress((void**)&Kh, g_Kh);
    cudaGetSymbolAddress((void**)&Kl, g_Kl);
    cudaGetSymbolAddress((void**)&Vh, g_Vh);
    cudaGetSymbolAddress((void**)&Vl, g_Vl);

    cudaFuncSetAttribute(gemm_imma_s8,
                         cudaFuncAttributeMaxDynamicSharedMemorySize, NST * STAGE_BYTES);
    cudaFuncSetAttribute(attn_mma,
                         cudaFuncAttributeMaxDynamicSharedMemorySize, 65536);

    // 0) quantize activations + weights
    quant_rows<<<SEQ, 256>>>(H, HID, Aqh, Aql, Asc);
    {
        dim3 bt(32, 8);
        colmax_part<<<dim3(QKV_N / 256, 16), 256>>>(Wa, HID, QKV_N, part);
        cvt_transpose_quant<<<dim3(QKV_N / 32, HID / 32), bt>>>(
            Wa, part, Wqah, Wqal, Wasc, HID, QKV_N);
        colmax_part<<<dim3(HID / 256, 16), 256>>>(Wp, HID, HID, part);
        cvt_transpose_quant<<<dim3(HID / 32, HID / 32), bt>>>(
            Wp, part, Wqph, Wqpl, Wpsc, HID, HID);
    }

    // 1) QKV GEMM (int8 IMMA) -> per-head hi/lo Q/K/V
    {
        dim3 g(QKV_N / 128, SEQ / 128);
        gemm_imma_s8<<<g, 512, NST * STAGE_BYTES>>>(
            SEQ, QKV_N, HID, 1, Aqh, Aql, Asc, Wqah, Wqal, Wasc, ba, nullptr,
            Qh, Ql, Kh, Kl, Vh, Vl);
    }

    // 2) Tensorized causal attention -> fp32 attnC
    {
        dim3 g(SEQ / 128, NH);
        attn_mma<<<g, 256, 65536>>>(Qh, Ql, Kh, Kl, Vh, Vl, attnC);
    }

    // 3) quantize attention output, proj GEMM (int8 IMMA) -> out
    quant_rows<<<SEQ, 256>>>(attnC, HID, Cqh, Cql, Csc);
    {
        dim3 g(HID / 128, SEQ / 128);
        gemm_imma_s8<<<g, 512, NST * STAGE_BYTES>>>(
            SEQ, HID, HID, 0, Cqh, Cql, Csc, Wqph, Wqpl, Wpsc, bp, out,
            nullptr, nullptr, nullptr, nullptr, nullptr, nullptr);
    }
}

// round 15
// speedup vs baseline: 4.5584x; 4.5584x over previous
#include <cuda_runtime.h>
#include <cuda_fp16.h>
#include <math_constants.h>
#include <cstdint>

#define SEQ 2048
#define HID 1024
#define NH  16
#define HD  64
#define QKV_N (3 * HID)

// ---------------------------------------------------------------------------
// Scratch (no dynamic allocation allowed) — fp16 operands
// ---------------------------------------------------------------------------
__device__ __align__(128) __half g_Af[SEQ * HID];        // hidden fp16
__device__ __align__(128) __half g_Waf[QKV_N * HID];     // w_attn^T fp16
__device__ __align__(128) __half g_Wpf[HID * HID];       // w_proj^T fp16
__device__ __align__(128) __half g_Cf[SEQ * HID];        // attn out fp16
// per-head QKV fp16, layout [NH][SEQ][64]
__device__ __align__(128) __half g_Qf[NH * SEQ * HD];
__device__ __align__(128) __half g_Kf[NH * SEQ * HD];
__device__ __align__(128) __half g_Vf[NH * SEQ * HD];

// ---------------------------------------------------------------------------
// Helpers (baseline PTX only)
// ---------------------------------------------------------------------------
__device__ __forceinline__ uint32_t smem_u32(const void* p) {
    uint32_t a;
    asm("{ .reg .u64 t; cvta.to.shared.u64 t, %1; cvt.u32.u64 %0, t; }"
        : "=r"(a) : "l"(p));
    return a;
}
__device__ __forceinline__ void cp_async16(uint32_t dst, const void* src) {
    asm volatile("cp.async.cg.shared.global [%0], [%1], 16;"
                 :: "r"(dst), "l"(src));
}
#define CP_COMMIT() asm volatile("cp.async.commit_group;" ::: "memory")
#define CP_WAIT(n)  asm volatile("cp.async.wait_group %0;" :: "n"(n) : "memory")

__device__ __forceinline__ void ldm_x4(uint32_t* r, uint32_t addr) {
    asm volatile("ldmatrix.sync.aligned.m8n8.x4.shared.b16 {%0,%1,%2,%3}, [%4];"
                 : "=r"(r[0]), "=r"(r[1]), "=r"(r[2]), "=r"(r[3]) : "r"(addr));
}
__device__ __forceinline__ void ldm_x4_t(uint32_t* r, uint32_t addr) {
    asm volatile("ldmatrix.sync.aligned.m8n8.x4.trans.shared.b16 {%0,%1,%2,%3}, [%4];"
                 : "=r"(r[0]), "=r"(r[1]), "=r"(r[2]), "=r"(r[3]) : "r"(addr));
}
__device__ __forceinline__ void mma_f16(float* d, const uint32_t* a,
                                        uint32_t b0, uint32_t b1) {
    asm volatile(
        "mma.sync.aligned.m16n8k16.row.col.f32.f16.f16.f32 "
        "{%0,%1,%2,%3}, {%4,%5,%6,%7}, {%8,%9}, {%0,%1,%2,%3};"
        : "+f"(d[0]), "+f"(d[1]), "+f"(d[2]), "+f"(d[3])
        : "r"(a[0]), "r"(a[1]), "r"(a[2]), "r"(a[3]), "r"(b0), "r"(b1));
}
__device__ __forceinline__ uint32_t pack_f16(float a, float b) {
    __half2 t = __floats2half2_rn(a, b);
    return *reinterpret_cast<uint32_t*>(&t);
}

// ---------------------------------------------------------------------------
// Conversion kernels
// ---------------------------------------------------------------------------
__global__ void cvt_f16(const float* __restrict__ x,
                        __half* __restrict__ y, int n4) {
    int i = blockIdx.x * blockDim.x + threadIdx.x;
    if (i >= n4) return;
    float4 v = reinterpret_cast<const float4*>(x)[i];
    uint2 w;
    w.x = pack_f16(v.x, v.y);
    w.y = pack_f16(v.z, v.w);
    reinterpret_cast<uint2*>(y)[i] = w;
}

// w[K][N] fp32 -> out[N][K] fp16 (transpose)
__global__ void cvt_transpose_f16(const float* __restrict__ w,
                                  __half* __restrict__ t, int K, int N) {
    __shared__ float tile[32][33];
    int n0 = blockIdx.x * 32, k0 = blockIdx.y * 32;
    int tx = threadIdx.x, ty = threadIdx.y;
#pragma unroll
    for (int j = 0; j < 4; j++)
        tile[ty + 8 * j][tx] = w[(size_t)(k0 + ty + 8 * j) * N + n0 + tx];
    __syncthreads();
#pragma unroll
    for (int j = 0; j < 4; j++)
        t[(size_t)(n0 + ty + 8 * j) * K + k0 + tx] =
            __float2half(tile[tx][ty + 8 * j]);
}

// ---------------------------------------------------------------------------
// fp16 GEMM via mma.sync m16n8k16: C[M,N] = A[M,K] @ Bt[N,K]^T + bias
// 512 threads (16 warps, 4/SMSP), warp tile 32x32, 4-stage cp.async pipeline.
// mode 0: fp32 C + bias. mode 1: QKV split fp16 per head.
// ---------------------------------------------------------------------------
#define PITCH 80
#define MAT_BYTES (128 * PITCH)        // 10240
#define STAGE_BYTES (2 * MAT_BYTES)    // 20480 (A + B)
#define NST 4

__global__ __launch_bounds__(512, 1) void gemm_mma_f16(
    int M, int N, int K, int mode,
    const __half* __restrict__ A, const __half* __restrict__ B,
    const float* __restrict__ bias, float* __restrict__ C,
    __half* __restrict__ qf, __half* __restrict__ kf, __half* __restrict__ vf)
{
    extern __shared__ char sm[];
    const uint32_t sbase = smem_u32(sm);
    const int tid = threadIdx.x;
    const int lane = tid & 31;
    const int warp = tid >> 5;      // 0..15
    const int wm = warp & 3;        // 32-row band
    const int wn = warp >> 2;       // 32-col band
    const int m0 = blockIdx.y * 128;
    const int n0 = blockIdx.x * 128;

    const __half* srcs[2] = { A + (size_t)m0 * K, B + (size_t)n0 * K };

    float acc[2][4][4];
#pragma unroll
    for (int i = 0; i < 2; i++)
#pragma unroll
        for (int j = 0; j < 4; j++)
#pragma unroll
            for (int q = 0; q < 4; q++) acc[i][j][q] = 0.0f;

    // stage: 2 mats x 128 rows x 64B (BK = 32 fp16)
    auto load_stage = [&](int s, int kc) {
#pragma unroll
        for (int i = 0; i < 2; i++) {
            int t = tid + i * 512;
            int mat = t >> 9;
            int r = (t >> 2) & 127;
            int ch = t & 3;
            cp_async16(sbase + s * STAGE_BYTES + mat * MAT_BYTES + r * PITCH + ch * 16,
                       srcs[mat] + (size_t)r * K + kc * 32 + ch * 8);
        }
    };

    const int NC = K / 32;
#pragma unroll
    for (int s = 0; s < NST - 1; s++) {
        load_stage(s, s);
        CP_COMMIT();
    }

    const int g = lane >> 3;
    const int rl = lane & 7;

    for (int c = 0; c < NC; c++) {
        CP_WAIT(NST - 2);
        __syncthreads();

        const uint32_t st = sbase + (c % NST) * STAGE_BYTES;

#pragma unroll
        for (int k16 = 0; k16 < 2; k16++) {
            const int ch = k16 * 2 + (g >> 1);
            const int roff = rl + ((g & 1) << 3);

            uint32_t af[2][4];
#pragma unroll
            for (int mf = 0; mf < 2; mf++) {
                int row = wm * 32 + mf * 16 + roff;
                ldm_x4(af[mf], st + row * PITCH + ch * 16);
            }

            uint32_t bf[4][2];
#pragma unroll
            for (int ng = 0; ng < 2; ng++) {
                int row = wn * 32 + ng * 16 + roff;
                uint32_t r4[4];
                ldm_x4(r4, st + MAT_BYTES + row * PITCH + ch * 16);
                bf[2 * ng][0] = r4[0];     bf[2 * ng][1] = r4[2];
                bf[2 * ng + 1][0] = r4[1]; bf[2 * ng + 1][1] = r4[3];
            }

#pragma unroll
            for (int mf = 0; mf < 2; mf++)
#pragma unroll
                for (int nf = 0; nf < 4; nf++)
                    mma_f16(acc[mf][nf], af[mf], bf[nf][0], bf[nf][1]);
        }

        if (c + NST - 1 < NC)
            load_stage((c + NST - 1) % NST, c + NST - 1);
        CP_COMMIT();
    }

    // Epilogue
#pragma unroll
    for (int mf = 0; mf < 2; mf++) {
        int rbase = m0 + wm * 32 + mf * 16 + (lane >> 2);
#pragma unroll
        for (int nf = 0; nf < 4; nf++) {
            int col = n0 + wn * 32 + nf * 8 + (lane & 3) * 2;
            float2 bv = *reinterpret_cast<const float2*>(&bias[col]);
            float a0 = acc[mf][nf][0] + bv.x, a1 = acc[mf][nf][1] + bv.y;
            float a2 = acc[mf][nf][2] + bv.x, a3 = acc[mf][nf][3] + bv.y;
            if (mode == 0) {
                float2 o0 = {a0, a1}, o1 = {a2, a3};
                *reinterpret_cast<float2*>(&C[(size_t)rbase * N + col]) = o0;
                *reinterpret_cast<float2*>(&C[(size_t)(rbase + 8) * N + col]) = o1;
            } else {
                int sec = col >> 10;
                int head = (col & 1023) >> 6;
                int dim = col & 63;
                __half* d = (sec == 0) ? qf : (sec == 1) ? kf : vf;
                size_t o0 = ((size_t)head * SEQ + rbase) * HD + dim;
                size_t o1 = o0 + 8 * HD;
                *reinterpret_cast<uint32_t*>(&d[o0]) = pack_f16(a0, a1);
                *reinterpret_cast<uint32_t*>(&d[o1]) = pack_f16(a2, a3);
            }
        }
    }
}

// ---------------------------------------------------------------------------
// fp16 causal flash attention, balanced 2-pass.
// Grid (8, NH); CTA processes q-tiles qb=blockIdx.x and qb=15-blockIdx.x
// (constant 36 KV-tile units per CTA). 256 threads = 8 warps x 16 rows.
// Smem: KV stages (2 x 16KB: K 8KB + V 8KB) at 0..32KB, Q tile at 32KB..48KB.
// Output: fp16 C [SEQ][HID] (feeds proj GEMM directly).
// ---------------------------------------------------------------------------
__global__ __launch_bounds__(256, 1) void attn_mma_f16(
    const __half* __restrict__ Qf_, const __half* __restrict__ Kf_,
    const __half* __restrict__ Vf_, __half* __restrict__ Cf)
{
    extern __shared__ char sm[];
    const uint32_t sb = smem_u32(sm);
    const uint32_t sq = sb + 32768;
    const int h = blockIdx.y;
    const int tid = threadIdx.x;
    const int lane = tid & 31;
    const int warp = tid >> 5;
    const size_t hb = (size_t)h * SEQ * HD;
    const float scale = 0.125f;

    const __half* Kh = Kf_ + hb;
    const __half* Vh = Vf_ + hb;

    for (int pass = 0; pass < 2; pass++) {
        const int qb = pass == 0 ? (int)blockIdx.x : 15 - (int)blockIdx.x;
        const int qbase = qb * 128;

        // ---- Load Q tile (128 rows fp16) to smem, extract A-fragments ----
        for (int i = tid; i < 128 * 8; i += 256) {
            int r = i >> 3, ch = i & 7;
            cp_async16(sq + r * 128 + ((ch ^ (r & 7)) * 16),
                       Qf_ + hb + (size_t)(qbase + r) * HD + ch * 8);
        }
        CP_COMMIT(); CP_WAIT(0);
        __syncthreads();

        uint32_t qfr[4][4];
        {
            int row = warp * 16 + (lane & 15);
#pragma unroll
            for (int ks = 0; ks < 4; ks++) {
                int ch = ks * 2 + (lane >> 4);
                ldm_x4(qfr[ks], sq + row * 128 + ((ch ^ (row & 7)) * 16));
            }
        }
        __syncthreads();

        float o[8][4];
#pragma unroll
        for (int i = 0; i < 8; i++)
#pragma unroll
            for (int j = 0; j < 4; j++) o[i][j] = 0.0f;
        float m0v = -CUDART_INF_F, m1v = -CUDART_INF_F;
        float l0v = 0.0f, l1v = 0.0f;

        auto load_kv = [&](int s, int t) {
#pragma unroll
            for (int i = 0; i < 4; i++) {
                int idx = tid + i * 256;
                int mat = idx >> 9;            // 0: K, 1: V
                int r = (idx >> 3) & 63;
                int ch = idx & 7;
                const __half* src = mat ? Vh : Kh;
                cp_async16(sb + s * 16384 + mat * 8192 + r * 128 + ((ch ^ (r & 7)) * 16),
                           src + (size_t)(t * 64 + r) * HD + ch * 8);
            }
            CP_COMMIT();
        };

        load_kv(0, 0);

        const int ntiles = 2 * qb + 2;
        for (int t = 0; t < ntiles; t++) {
            if (t + 1 < ntiles) {
                load_kv((t + 1) & 1, t + 1);
                CP_WAIT(1);
            } else {
                CP_WAIT(0);
            }
            __syncthreads();

            const uint32_t st = sb + (t & 1) * 16384;
            const bool active = (t * 64 <= qbase + warp * 16 + 15);

            if (active) {
                // ---- S = Q K^T (kg pairs for ILP) ----
                float s[8][4];
#pragma unroll
                for (int i = 0; i < 8; i++)
#pragma unroll
                    for (int j = 0; j < 4; j++) s[i][j] = 0.0f;

#pragma unroll
                for (int ks = 0; ks < 4; ks++) {
#pragma unroll
                    for (int kp = 0; kp < 2; kp++) {
                        uint32_t r4[2][4];
#pragma unroll
                        for (int j = 0; j < 2; j++) {
                            int key = (kp * 2 + j) * 16 + (lane & 15);
                            int ch = ks * 2 + (lane >> 4);
                            ldm_x4(r4[j], st + key * 128 + ((ch ^ (key & 7)) * 16));
                        }
                        mma_f16(s[4 * kp + 0], qfr[ks], r4[0][0], r4[0][2]);
                        mma_f16(s[4 * kp + 1], qfr[ks], r4[0][1], r4[0][3]);
                        mma_f16(s[4 * kp + 2], qfr[ks], r4[1][0], r4[1][2]);
                        mma_f16(s[4 * kp + 3], qfr[ks], r4[1][1], r4[1][3]);
                    }
                }

                // ---- scale + causal mask + online softmax ----
                const bool masked = (t >= 2 * qb);
                const int gr = lane >> 2;
                const int c2 = (lane & 3) * 2;
                const int gq0 = qbase + warp * 16 + gr;
                float mx0 = -CUDART_INF_F, mx1 = -CUDART_INF_F;
#pragma unroll
                for (int nf = 0; nf < 8; nf++) {
#pragma unroll
                    for (int j = 0; j < 2; j++) {
                        s[nf][j]     *= scale;
                        s[nf][2 + j] *= scale;
                        if (masked) {
                            int gk = t * 64 + nf * 8 + c2 + j;
                            if (gk > gq0)     s[nf][j]     = -CUDART_INF_F;
                            if (gk > gq0 + 8) s[nf][2 + j] = -CUDART_INF_F;
                        }
                        mx0 = fmaxf(mx0, s[nf][j]);
                        mx1 = fmaxf(mx1, s[nf][2 + j]);
                    }
                }
                mx0 = fmaxf(mx0, __shfl_xor_sync(0xffffffffu, mx0, 1));
                mx0 = fmaxf(mx0, __shfl_xor_sync(0xffffffffu, mx0, 2));
                mx1 = fmaxf(mx1, __shfl_xor_sync(0xffffffffu, mx1, 1));
                mx1 = fmaxf(mx1, __shfl_xor_sync(0xffffffffu, mx1, 2));

                float mn0 = fmaxf(m0v, mx0), mn1 = fmaxf(m1v, mx1);
                float sum0 = 0.0f, sum1 = 0.0f;
#pragma unroll
                for (int nf = 0; nf < 8; nf++) {
#pragma unroll
                    for (int j = 0; j < 2; j++) {
                        float p0 = __expf(s[nf][j] - mn0);
                        float p1 = __expf(s[nf][2 + j] - mn1);
                        s[nf][j] = p0;
                        s[nf][2 + j] = p1;
                        sum0 += p0;
                        sum1 += p1;
                    }
                }
                sum0 += __shfl_xor_sync(0xffffffffu, sum0, 1);
                sum0 += __shfl_xor_sync(0xffffffffu, sum0, 2);
                sum1 += __shfl_xor_sync(0xffffffffu, sum1, 1);
                sum1 += __shfl_xor_sync(0xffffffffu, sum1, 2);

                float corr0 = __expf(m0v - mn0), corr1 = __expf(m1v - mn1);
                l0v = l0v * corr0 + sum0;
                l1v = l1v * corr1 + sum1;
                m0v = mn0; m1v = mn1;
#pragma unroll
                for (int nf = 0; nf < 8; nf++) {
                    o[nf][0] *= corr0; o[nf][1] *= corr0;
                    o[nf][2] *= corr1; o[nf][3] *= corr1;
                }

                // ---- O += P V (dg pairs for ILP) ----
#pragma unroll
                for (int ks = 0; ks < 4; ks++) {
                    uint32_t pa[4];
#pragma unroll
                    for (int half = 0; half < 2; half++) {
                        pa[half * 2]     = pack_f16(s[2 * ks + half][0], s[2 * ks + half][1]);
                        pa[half * 2 + 1] = pack_f16(s[2 * ks + half][2], s[2 * ks + half][3]);
                    }
#pragma unroll
                    for (int dp = 0; dp < 2; dp++) {
                        uint32_t r4[2][4];
#pragma unroll
                        for (int j = 0; j < 2; j++) {
                            int dg = dp * 2 + j;
                            int key = ks * 16 + (lane & 15);
                            int ch = dg * 2 + (lane >> 4);
                            ldm_x4_t(r4[j], st + 8192 + key * 128 + ((ch ^ (key & 7)) * 16));
                        }
                        mma_f16(o[4 * dp + 0], pa, r4[0][0], r4[0][1]);
                        mma_f16(o[4 * dp + 1], pa, r4[0][2], r4[0][3]);
                        mma_f16(o[4 * dp + 2], pa, r4[1][0], r4[1][1]);
                        mma_f16(o[4 * dp + 3], pa, r4[1][2], r4[1][3]);
                    }
                }
            }
            __syncthreads();
        }

        // ---- Finalize: O /= l, write fp16 to Cf ----
        const float inv0 = 1.0f / l0v, inv1 = 1.0f / l1v;
        const int row0 = qbase + warp * 16 + (lane >> 2);
        const int col0 = h * HD + (lane & 3) * 2;
#pragma unroll
        for (int nf = 0; nf < 8; nf++) {
            int col = col0 + nf * 8;
            *reinterpret_cast<uint32_t*>(&Cf[(size_t)row0 * HID + col]) =
                pack_f16(o[nf][0] * inv0, o[nf][1] * inv0);
            *reinterpret_cast<uint32_t*>(&Cf[(size_t)(row0 + 8) * HID + col]) =
                pack_f16(o[nf][2] * inv1, o[nf][3] * inv1);
        }
        __syncthreads();
    }
}

// ---------------------------------------------------------------------------
extern "C" void kernel_launch(void* const* d_in, const int* in_sizes, int n_in,
                              void* d_out, int out_size)
{
    const float* H  = (const float*)d_in[0];
    const float* Wa = (const float*)d_in[1];
    const float* ba = (const float*)d_in[2];
    const float* Wp = (const float*)d_in[3];
    const float* bp = (const float*)d_in[4];
    float* out = (float*)d_out;

    __half *Af, *Waf, *Wpf, *Cf, *Qf, *Kf, *Vf;
    cudaGetSymbolAddress((void**)&Af, g_Af);
    cudaGetSymbolAddress((void**)&Waf, g_Waf);
    cudaGetSymbolAddress((void**)&Wpf, g_Wpf);
    cudaGetSymbolAddress((void**)&Cf, g_Cf);
    cudaGetSymbolAddress((void**)&Qf, g_Qf);
    cudaGetSymbolAddress((void**)&Kf, g_Kf);
    cudaGetSymbolAddress((void**)&Vf, g_Vf);

    cudaFuncSetAttribute(gemm_mma_f16,
                         cudaFuncAttributeMaxDynamicSharedMemorySize, NST * STAGE_BYTES);
    cudaFuncSetAttribute(attn_mma_f16,
                         cudaFuncAttributeMaxDynamicSharedMemorySize, 49152);

    // 0) fp16 conversions
    {
        int n4 = SEQ * HID / 4;
        cvt_f16<<<(n4 + 255) / 256, 256>>>(H, Af, n4);
        dim3 bt(32, 8);
        cvt_transpose_f16<<<dim3(QKV_N / 32, HID / 32), bt>>>(Wa, Waf, HID, QKV_N);
        cvt_transpose_f16<<<dim3(HID / 32, HID / 32), bt>>>(Wp, Wpf, HID, HID);
    }

    // 1) QKV GEMM (fp16) -> per-head Q/K/V fp16
    {
        dim3 g(QKV_N / 128, SEQ / 128);
        gemm_mma_f16<<<g, 512, NST * STAGE_BYTES>>>(
            SEQ, QKV_N, HID, 1, Af, Waf, ba, nullptr, Qf, Kf, Vf);
    }

    // 2) fp16 causal attention (balanced 2-pass) -> Cf fp16
    {
        dim3 g(8, NH);
        attn_mma_f16<<<g, 256, 49152>>>(Qf, Kf, Vf, Cf);
    }

    // 3) Output projection (fp16) -> out fp32 + bias
    {
        dim3 g(HID / 128, SEQ / 128);
        gemm_mma_f16<<<g, 512, NST * STAGE_BYTES>>>(
            SEQ, HID, HID, 0, Cf, Wpf, bp, out, nullptr, nullptr, nullptr);
    }
}